// round 14
// baseline (speedup 1.0000x reference)
#include <cuda_runtime.h>
#include <cuda_bf16.h>
#include <math.h>
#include <cstdint>

#define NN 8192
#define HD 256

typedef unsigned long long u64;

// Scratch (device globals: allocation-free rule).
static __device__ float g_fused[NN * HD];                         // 8 MB
static __device__ float g_hn[NN * HD];                            // 8 MB (fp32, for rescore)
static __device__ __nv_bfloat16 g_sh[NN * HD];                    // 4 MB (hi)
static __device__ __nv_bfloat16 g_sm[NN * HD];                    // 4 MB (mid)
static __device__ __nv_bfloat16 g_sl[NN * HD];                    // 4 MB (lo)
static __device__ float g_sim[(size_t)NN * NN];                   // 256 MB

// ---- packed f32x2 helpers (FFMA2 path, PTX-only) ---------------------------
__device__ __forceinline__ void fma2(u64 &d, u64 a, u64 b) {
    asm("fma.rn.f32x2 %0, %1, %2, %3;" : "=l"(d) : "l"(a), "l"(b), "l"(d));
}
__device__ __forceinline__ u64 dup2(float x) {
    u64 r; asm("mov.b64 %0, {%1, %1};" : "=l"(r) : "f"(x)); return r;
}
__device__ __forceinline__ void unpack2(u64 v, float &lo, float &hi) {
    asm("mov.b64 {%0, %1}, %2;" : "=f"(lo), "=f"(hi) : "l"(v));
}
__device__ __forceinline__ uint32_t smem_to_u32(const void* p) {
    uint32_t a;
    asm("{ .reg .u64 t; cvta.to.shared.u64 t, %1; cvt.u32.u64 %0, t; }" : "=r"(a) : "l"(p));
    return a;
}

// ---------------------------------------------------------------------------
// Encoder (unchanged): 128x128 tile of sum_m relu(X_m W_m + b_m).
// ---------------------------------------------------------------------------
__device__ __forceinline__ void enc_gemm_one(
    float (&total)[8][8],
    const float* __restrict__ X, const float* __restrict__ W,
    const float* __restrict__ bias,
    int K, int rowBase, int colBase, int tid,
    float (*As)[8][128], float (*Bs)[8][128])
{
    const int arow = tid >> 1;
    const int akx  = (tid & 1) * 4;
    const int bk   = tid >> 5;
    const int bn   = (tid & 31) * 4;
    const int ty   = tid >> 4;
    const int tx   = tid & 15;

    const float* aPtr = X + (size_t)(rowBase + arow) * K + akx;
    const float* bPtr = W + (size_t)bk * HD + colBase + bn;

    u64 acc2[4][8];
    #pragma unroll
    for (int i = 0; i < 4; i++)
        #pragma unroll
        for (int j = 0; j < 8; j++) acc2[i][j] = 0ULL;

    const int ntiles = K >> 3;

    float4 a4 = *(const float4*)aPtr;
    float4 b4 = *(const float4*)bPtr;
    As[0][akx + 0][arow] = a4.x; As[0][akx + 1][arow] = a4.y;
    As[0][akx + 2][arow] = a4.z; As[0][akx + 3][arow] = a4.w;
    *(float4*)&Bs[0][bk][bn] = b4;
    __syncthreads();

    for (int t = 0; t < ntiles; ++t) {
        const int cur = t & 1;
        if (t + 1 < ntiles) {
            a4 = *(const float4*)(aPtr + (t + 1) * 8);
            b4 = *(const float4*)(bPtr + (size_t)(t + 1) * 8 * HD);
        }
        #pragma unroll
        for (int kk = 0; kk < 8; kk++) {
            ulonglong2 a01 = *(const ulonglong2*)&As[cur][kk][ty * 8];
            ulonglong2 a23 = *(const ulonglong2*)&As[cur][kk][ty * 8 + 4];
            float4 B0 = *(const float4*)&Bs[cur][kk][tx * 8];
            float4 B1 = *(const float4*)&Bs[cur][kk][tx * 8 + 4];
            u64 brd[8];
            brd[0] = dup2(B0.x); brd[1] = dup2(B0.y);
            brd[2] = dup2(B0.z); brd[3] = dup2(B0.w);
            brd[4] = dup2(B1.x); brd[5] = dup2(B1.y);
            brd[6] = dup2(B1.z); brd[7] = dup2(B1.w);
            #pragma unroll
            for (int j = 0; j < 8; j++) {
                fma2(acc2[0][j], a01.x, brd[j]);
                fma2(acc2[1][j], a01.y, brd[j]);
                fma2(acc2[2][j], a23.x, brd[j]);
                fma2(acc2[3][j], a23.y, brd[j]);
            }
        }
        if (t + 1 < ntiles) {
            const int nxt = cur ^ 1;
            As[nxt][akx + 0][arow] = a4.x; As[nxt][akx + 1][arow] = a4.y;
            As[nxt][akx + 2][arow] = a4.z; As[nxt][akx + 3][arow] = a4.w;
            *(float4*)&Bs[nxt][bk][bn] = b4;
        }
        __syncthreads();
    }

    const int col = colBase + tx * 8;
    float bb[8];
    #pragma unroll
    for (int j = 0; j < 8; j++) bb[j] = bias[col + j];
    #pragma unroll
    for (int i2 = 0; i2 < 4; i2++)
        #pragma unroll
        for (int j = 0; j < 8; j++) {
            float lo, hi;
            unpack2(acc2[i2][j], lo, hi);
            total[2 * i2 + 0][j] += fmaxf(lo + bb[j], 0.0f);
            total[2 * i2 + 1][j] += fmaxf(hi + bb[j], 0.0f);
        }
}

__global__ __launch_bounds__(256, 1)
void enc_kernel(const float* __restrict__ X0, const float* __restrict__ W0, const float* __restrict__ b0,
                const float* __restrict__ X1, const float* __restrict__ W1, const float* __restrict__ b1,
                const float* __restrict__ X2, const float* __restrict__ W2, const float* __restrict__ b2)
{
    __shared__ __align__(16) float As[2][8][128];
    __shared__ __align__(16) float Bs[2][8][128];
    const int tid = threadIdx.x;
    const int rowBase = blockIdx.y * 128;
    const int colBase = blockIdx.x * 128;

    float total[8][8];
    #pragma unroll
    for (int i = 0; i < 8; i++)
        #pragma unroll
        for (int j = 0; j < 8; j++) total[i][j] = 0.0f;

    enc_gemm_one(total, X0, W0, b0, 1024, rowBase, colBase, tid, As, Bs);
    enc_gemm_one(total, X1, W1, b1,  768, rowBase, colBase, tid, As, Bs);
    enc_gemm_one(total, X2, W2, b2,  512, rowBase, colBase, tid, As, Bs);

    const int ty = tid >> 4, tx = tid & 15;
    const int row = rowBase + ty * 8;
    const int col = colBase + tx * 8;
    #pragma unroll
    for (int i = 0; i < 8; i++) {
        float4 o0 = make_float4(total[i][0], total[i][1], total[i][2], total[i][3]);
        float4 o1 = make_float4(total[i][4], total[i][5], total[i][6], total[i][7]);
        *(float4*)&g_fused[(size_t)(row + i) * HD + col]     = o0;
        *(float4*)&g_fused[(size_t)(row + i) * HD + col + 4] = o1;
    }
}

// ---------------------------------------------------------------------------
// Row normalize + fp32 hn + bf16x3 split (h + m + l).
// ---------------------------------------------------------------------------
__global__ void norm_kernel()
{
    const int tid  = threadIdx.x;
    const int lane = tid & 31;
    const int warp = tid >> 5;
    const int row  = blockIdx.x * 8 + warp;

    const float* fr = g_fused + (size_t)row * HD;
    float v[8];
    float ss = 0.0f;
    #pragma unroll
    for (int i = 0; i < 8; i++) {
        float x = fr[lane + i * 32] / 3.0f;
        v[i] = x;
        ss += x * x;
    }
    #pragma unroll
    for (int off = 16; off > 0; off >>= 1)
        ss += __shfl_xor_sync(0xffffffffu, ss, off);
    const float den = sqrtf(ss) + 1e-8f;
    #pragma unroll
    for (int i = 0; i < 8; i++) {
        const float x = v[i] / den;
        const size_t o = (size_t)row * HD + lane + i * 32;
        g_hn[o] = x;
        __nv_bfloat16 h = __float2bfloat16(x);
        float r1 = x - __bfloat162float(h);
        __nv_bfloat16 m = __float2bfloat16(r1);
        float r2 = r1 - __bfloat162float(m);
        __nv_bfloat16 l = __float2bfloat16(r2);
        g_sh[o] = h; g_sm[o] = m; g_sl[o] = l;
    }
}

// ---------------------------------------------------------------------------
// sim = hn @ hn^T via mma.sync.m16n8k16.bf16, bf16x3 split, 6 products,
// fp32 accumulators. B fragments hoisted across the A-split loop (LDSM cut).
// FILTER PRECISION ONLY (~2e-6).
// ---------------------------------------------------------------------------
#define KC 32
#define ROWB 80
#define TILE_BYTES (128 * ROWB)
#define SIM_SMEM (6 * TILE_BYTES)

__device__ __forceinline__ void ldsm_x4(uint32_t (&r)[4], uint32_t addr) {
    asm volatile("ldmatrix.sync.aligned.m8n8.x4.shared.b16 {%0,%1,%2,%3}, [%4];"
                 : "=r"(r[0]), "=r"(r[1]), "=r"(r[2]), "=r"(r[3]) : "r"(addr));
}
__device__ __forceinline__ void ldsm_x2(uint32_t (&r)[2], uint32_t addr) {
    asm volatile("ldmatrix.sync.aligned.m8n8.x2.shared.b16 {%0,%1}, [%2];"
                 : "=r"(r[0]), "=r"(r[1]) : "r"(addr));
}
__device__ __forceinline__ void mma_bf16(float (&d)[4], const uint32_t (&a)[4],
                                         const uint32_t (&b)[2]) {
    asm volatile("mma.sync.aligned.m16n8k16.row.col.f32.bf16.bf16.f32 "
                 "{%0,%1,%2,%3}, {%4,%5,%6,%7}, {%8,%9}, {%0,%1,%2,%3};"
                 : "+f"(d[0]), "+f"(d[1]), "+f"(d[2]), "+f"(d[3])
                 : "r"(a[0]), "r"(a[1]), "r"(a[2]), "r"(a[3]), "r"(b[0]), "r"(b[1]));
}

__global__ __launch_bounds__(256, 2)
void sim_mma_kernel()
{
    const int bx = blockIdx.x, by = blockIdx.y;
    if (by > bx) return;

    extern __shared__ __align__(16) char smem[];
    const uint32_t sbase = smem_to_u32(smem);
    const int tid   = threadIdx.x;
    const int lane  = tid & 31;
    const int wid   = tid >> 5;
    const int warpM = wid & 1;
    const int warpN = wid >> 1;
    const int rowBase = by * 128;
    const int colBase = bx * 128;

    const __nv_bfloat16* srcs[6] = {g_sh, g_sm, g_sl, g_sh, g_sm, g_sl};

    float acc[4][4][4];
    #pragma unroll
    for (int mt = 0; mt < 4; mt++)
        #pragma unroll
        for (int nt = 0; nt < 4; nt++)
            #pragma unroll
            for (int r = 0; r < 4; r++) acc[mt][nt][r] = 0.0f;

    const uint32_t aBase = (uint32_t)((warpM * 64 + (lane & 15)) * ROWB + (lane >> 4) * 16);
    const uint32_t bBase = (uint32_t)((warpN * 32 + (lane & 7)) * ROWB + ((lane >> 3) & 1) * 16);

    for (int ch = 0; ch < 8; ++ch) {
        const int ko = ch * KC;
        #pragma unroll
        for (int t = 0; t < 6; ++t) {
            const int rb = (t < 3) ? rowBase : colBase;
            const __nv_bfloat16* src = srcs[t];
            #pragma unroll
            for (int q = 0; q < 2; ++q) {
                const int idx = q * 256 + tid;
                const int r = idx >> 2;
                const int c = (idx & 3) * 8;
                uint4 val = *(const uint4*)&src[(size_t)(rb + r) * HD + ko + c];
                *(uint4*)(smem + t * TILE_BYTES + r * ROWB + c * 2) = val;
            }
        }
        __syncthreads();

        #pragma unroll
        for (int ks = 0; ks < 2; ++ks) {
            const uint32_t kb = (uint32_t)(ks * 32);
            // hoist ALL B fragments (3 splits x 4 n-tiles) once per k16-step
            uint32_t bfr[3][4][2];
            #pragma unroll
            for (int bs = 0; bs < 3; ++bs)
                #pragma unroll
                for (int nt = 0; nt < 4; ++nt)
                    ldsm_x2(bfr[bs][nt], sbase + (3 + bs) * TILE_BYTES + bBase + nt * 8 * ROWB + kb);
            #pragma unroll
            for (int as = 0; as < 3; ++as) {
                uint32_t afrag[4][4];
                #pragma unroll
                for (int mt = 0; mt < 4; mt++)
                    ldsm_x4(afrag[mt], sbase + as * TILE_BYTES + aBase + mt * 16 * ROWB + kb);
                const int nb = (as == 0) ? 3 : ((as == 1) ? 2 : 1);
                for (int bs = 0; bs < nb; ++bs) {
                    #pragma unroll
                    for (int nt = 0; nt < 4; nt++)
                        #pragma unroll
                        for (int mt = 0; mt < 4; mt++)
                            mma_bf16(acc[mt][nt], afrag[mt], bfr[bs][nt]);
                }
            }
        }
        __syncthreads();
    }

    const int r0 = lane >> 2;
    const int c0 = (lane & 3) * 2;
    #pragma unroll
    for (int mt = 0; mt < 4; mt++) {
        #pragma unroll
        for (int nt = 0; nt < 4; nt++) {
            const int rg = rowBase + warpM * 64 + mt * 16 + r0;
            const int cg = colBase + warpN * 32 + nt * 8 + c0;
            *(float2*)&g_sim[(size_t)rg * NN + cg]       = make_float2(acc[mt][nt][0], acc[mt][nt][1]);
            *(float2*)&g_sim[(size_t)(rg + 8) * NN + cg] = make_float2(acc[mt][nt][2], acc[mt][nt][3]);
        }
    }
    if (by != bx) {
        #pragma unroll
        for (int mt = 0; mt < 4; mt++) {
            #pragma unroll
            for (int nt = 0; nt < 4; nt++) {
                const int rg = rowBase + warpM * 64 + mt * 16 + r0;
                const int cg = colBase + warpN * 32 + nt * 8 + c0;
                g_sim[(size_t)cg * NN + rg]           = acc[mt][nt][0];
                g_sim[(size_t)(cg + 1) * NN + rg]     = acc[mt][nt][1];
                g_sim[(size_t)cg * NN + rg + 8]       = acc[mt][nt][2];
                g_sim[(size_t)(cg + 1) * NN + rg + 8] = acc[mt][nt][3];
            }
        }
    }
}

// ---------------------------------------------------------------------------
// Top-16 per row, parallelized:
//  (1) per-warp privatized histograms (no cross-warp atomic contention)
//  (2) candidates (v >= bin_lo(b1) - 1e-5) into smem
//  (3) approx selection: each warp reg-selects top-16 of its 256-slice,
//      warp 0 merges 128 -> t16 (true 16th of approx values)
//  (4) rescore set = candidates with approx >= t16 - 2e-5 (includes winners)
//  (5) exact sequential-k fp32 rescore (R1-R3-identical chain) + exact top-16
// ---------------------------------------------------------------------------
__device__ __forceinline__ float key_val(u64 k) {
    unsigned u = (unsigned)(k >> 32);
    unsigned s = (u & 0x80000000u) ? (u ^ 0x80000000u) : ~u;
    return __uint_as_float(s);
}
__device__ __forceinline__ int bin_of(float v) {
    int b = (int)((v + 1.0f) * 128.0f);
    return max(0, min(255, b));
}

#define CAND_CAP 2048
#define RESC_CAP 144

__global__ __launch_bounds__(256)
void topk_kernel(float* __restrict__ out)
{
    const int row  = blockIdx.x;
    const int tid  = threadIdx.x;
    const int lane = tid & 31;
    const int wid  = tid >> 5;

    __shared__ unsigned hist8[8][256];
    __shared__ int s_b1;
    __shared__ unsigned candCnt;
    __shared__ u64  candKey[CAND_CAP];
    __shared__ float rowVec[HD];
    __shared__ u64  sTop[8][16];
    __shared__ u64  sFinal[16];
    __shared__ float s_t16;
    __shared__ int  rescIdx[RESC_CAP];
    __shared__ u64  rescKey[RESC_CAP];
    __shared__ unsigned rescCnt;
    __shared__ float s_keep;

    // zero-fill output row (d_out is poisoned)
    float4 z = make_float4(0.f, 0.f, 0.f, 0.f);
    float4* orow = (float4*)(out + (size_t)row * NN);
    #pragma unroll
    for (int i = 0; i < 8; i++) orow[tid + i * 256] = z;

    #pragma unroll
    for (int w = 0; w < 8; w++) hist8[w][tid] = 0u;
    if (tid == 0) { candCnt = 0u; rescCnt = 0u; }
    rowVec[tid] = g_hn[(size_t)row * HD + tid];
    __syncthreads();

    // load MMA sim row (diag -> -2), per-warp histogram
    float v[32];
    const float* srow = g_sim + (size_t)row * NN;
    #pragma unroll
    for (int j = 0; j < 32; j++) {
        const int c = tid + j * 256;
        float x = srow[c];
        v[j] = (c == row) ? -2.0f : x;
    }
    #pragma unroll
    for (int j = 0; j < 32; j++)
        atomicAdd(&hist8[wid][bin_of(v[j])], 1u);
    __syncthreads();

    // warp 0: b1 = max bin with suffix count >= 16 (sum of 8 warp histograms)
    if (wid == 0) {
        unsigned h[8];
        unsigned s = 0;
        #pragma unroll
        for (int q = 0; q < 8; q++) {
            unsigned t = 0;
            #pragma unroll
            for (int w = 0; w < 8; w++) t += hist8[w][lane * 8 + q];
            h[q] = t; s += t;
        }
        unsigned suf = s;
        #pragma unroll
        for (int off = 1; off < 32; off <<= 1) {
            unsigned o = __shfl_down_sync(0xffffffffu, suf, off);
            if (lane + off < 32) suf += o;
        }
        unsigned run = suf - s;
        int best = -1;
        #pragma unroll
        for (int q = 7; q >= 0; q--) {
            run += h[q];
            if (best < 0 && run >= 16u) best = lane * 8 + q;
        }
        #pragma unroll
        for (int off = 16; off > 0; off >>= 1) {
            int o = __shfl_xor_sync(0xffffffffu, best, off);
            best = max(best, o);
        }
        if (lane == 0) s_b1 = best;
    }
    __syncthreads();
    const float cutLo = (float)s_b1 / 128.0f - 1.0f - 1e-5f;

    // collect approx candidate keys, warp-aggregated append
    #pragma unroll
    for (int j = 0; j < 32; j++) {
        const bool p = (v[j] >= cutLo);
        const unsigned m = __ballot_sync(0xffffffffu, p);
        if (m == 0u) continue;
        const int leader = __ffs(m) - 1;
        unsigned base = 0;
        if (lane == leader) base = atomicAdd(&candCnt, (unsigned)__popc(m));
        base = __shfl_sync(0xffffffffu, base, leader);
        if (p) {
            const unsigned pos = base + __popc(m & ((1u << lane) - 1u));
            if (pos < CAND_CAP) {
                const int c = tid + j * 256;
                unsigned sb = __float_as_uint(v[j]);
                unsigned u = sb ^ ((unsigned)((int)sb >> 31) | 0x80000000u);
                candKey[pos] = ((u64)u << 32) | (unsigned)(~c);
            }
        }
    }
    __syncthreads();

    const int n = min((int)candCnt, CAND_CAP);

    // (3) parallel approx selection: warp w takes candKey[w*256 .. w*256+255]
    {
        u64 k[8];
        #pragma unroll
        for (int q = 0; q < 8; q++) {
            const int idx = wid * 256 + q * 32 + lane;
            k[q] = (idx < n) ? candKey[idx] : 0ULL;
        }
        u64 lmax = 0ULL;
        #pragma unroll
        for (int q = 0; q < 8; q++) if (k[q] > lmax) lmax = k[q];
        #pragma unroll 1
        for (int it = 0; it < 16; ++it) {
            u64 w = lmax;
            #pragma unroll
            for (int off = 16; off > 0; off >>= 1) {
                u64 o = __shfl_xor_sync(0xffffffffu, w, off);
                if (o > w) w = o;
            }
            if (lane == 0) sTop[wid][it] = w;
            if (lmax == w && w != 0ULL) {
                lmax = 0ULL;
                #pragma unroll
                for (int q = 0; q < 8; q++) {
                    if (k[q] == w) k[q] = 0ULL;
                    else if (k[q] > lmax) lmax = k[q];
                }
            }
        }
    }
    __syncthreads();

    // warp 0: merge 8x16 -> global approx top-16 and t16
    if (wid == 0) {
        u64 cand[4];
        #pragma unroll
        for (int q = 0; q < 4; q++) {
            const int idx = lane * 4 + q;
            cand[q] = sTop[idx >> 4][idx & 15];
        }
        u64 lm = cand[0];
        if (cand[1] > lm) lm = cand[1];
        if (cand[2] > lm) lm = cand[2];
        if (cand[3] > lm) lm = cand[3];
        #pragma unroll 1
        for (int it = 0; it < 16; ++it) {
            u64 w = lm;
            #pragma unroll
            for (int off = 16; off > 0; off >>= 1) {
                u64 o = __shfl_xor_sync(0xffffffffu, w, off);
                if (o > w) w = o;
            }
            if (lane == 0) sFinal[it] = w;
            if (lm == w && w != 0ULL) {
                lm = 0ULL;
                #pragma unroll
                for (int q = 0; q < 4; q++) {
                    if (cand[q] == w) cand[q] = 0ULL;
                    else if (cand[q] > lm) lm = cand[q];
                }
            }
        }
        if (lane == 0) s_t16 = key_val(sFinal[15]);
    }
    __syncthreads();

    // (4) rescore set: all candidates with approx >= t16 - 2e-5 (winners incl.)
    const float thr = s_t16 - 2e-5f;
    for (int i = tid; i < n; i += 256) {
        const u64 k = candKey[i];
        if (key_val(k) >= thr) {
            const unsigned pos = atomicAdd(&rescCnt, 1u);
            if (pos < RESC_CAP) rescIdx[pos] = (int)(~(unsigned)(k & 0xffffffffu));
        }
    }
    __syncthreads();

    const int m = min((int)rescCnt, RESC_CAP);

    // (5) exact rescore: one thread per candidate, sequential k=0..255 fmaf
    // chain (bitwise identical to the R1-R3 passing sim computation).
    for (int i = tid; i < m; i += 256) {
        const int c = rescIdx[i];
        const float4* cv4 = (const float4*)(g_hn + (size_t)c * HD);
        float acc = 0.0f;
        #pragma unroll 4
        for (int k4 = 0; k4 < HD / 4; k4++) {
            float4 b = cv4[k4];
            acc = fmaf(rowVec[4 * k4 + 0], b.x, acc);
            acc = fmaf(rowVec[4 * k4 + 1], b.y, acc);
            acc = fmaf(rowVec[4 * k4 + 2], b.z, acc);
            acc = fmaf(rowVec[4 * k4 + 3], b.w, acc);
        }
        unsigned sb = __float_as_uint(acc);
        unsigned u = sb ^ ((unsigned)((int)sb >> 31) | 0x80000000u);
        rescKey[i] = ((u64)u << 32) | (unsigned)(~c);
    }
    __syncthreads();

    // warp 0: exact top-16 over m rescored candidates (m small)
    if (wid == 0) {
        for (int it = 0; it < 16; ++it) {
            u64 lm = 0ULL;
            for (int i = lane; i < m; i += 32) {
                u64 k = rescKey[i];
                if (k > lm) lm = k;
            }
            u64 w = lm;
            #pragma unroll
            for (int off = 16; off > 0; off >>= 1) {
                u64 o = __shfl_xor_sync(0xffffffffu, w, off);
                if (o > w) w = o;
            }
            if (lane == 0) sFinal[it] = w;
            for (int i = lane; i < m; i += 32)
                if (rescKey[i] == w) rescKey[i] = 0ULL;
        }
        if (lane == 0) {
            float sum = 0.0f;
            #pragma unroll
            for (int it = 0; it < 16; ++it) sum += key_val(sFinal[it]);
            s_keep = (sum / 16.0f > 0.5f) ? 1.0f : 0.0f;
        }
    }
    __syncthreads();

    if (tid < 16) {
        const u64 k = sFinal[tid];
        const int c = (int)(~(unsigned)(k & 0xffffffffu));
        out[(size_t)row * NN + c] = key_val(k) * s_keep;
    }
}

// ---------------------------------------------------------------------------
extern "C" void kernel_launch(void* const* d_in, const int* in_sizes, int n_in,
                              void* d_out, int out_size)
{
    const float* x_img = (const float*)d_in[0];
    const float* W_img = (const float*)d_in[1];
    const float* b_img = (const float*)d_in[2];
    const float* x_txt = (const float*)d_in[3];
    const float* W_txt = (const float*)d_in[4];
    const float* b_txt = (const float*)d_in[5];
    const float* x_aud = (const float*)d_in[6];
    const float* W_aud = (const float*)d_in[7];
    const float* b_aud = (const float*)d_in[8];
    float* out = (float*)d_out;

    cudaFuncSetAttribute(sim_mma_kernel, cudaFuncAttributeMaxDynamicSharedMemorySize, SIM_SMEM);

    enc_kernel<<<dim3(2, 64), 256>>>(x_img, W_img, b_img,
                                     x_txt, W_txt, b_txt,
                                     x_aud, W_aud, b_aud);
    norm_kernel<<<1024, 256>>>();
    sim_mma_kernel<<<dim3(64, 64), 256, SIM_SMEM>>>();
    topk_kernel<<<NN, 256>>>(out);
}

// round 15
// speedup vs baseline: 1.0421x; 1.0421x over previous
#include <cuda_runtime.h>
#include <cuda_bf16.h>
#include <math.h>
#include <cstdint>

#define NN 8192
#define HD 256

typedef unsigned long long u64;

// Scratch (device globals: allocation-free rule).
static __device__ float g_fused[NN * HD];                         // 8 MB
static __device__ float g_hn[NN * HD];                            // 8 MB (fp32, for rescore)
static __device__ __nv_bfloat16 g_sh[NN * HD];                    // 4 MB (hi)
static __device__ __nv_bfloat16 g_sm[NN * HD];                    // 4 MB (mid)
static __device__ __nv_bfloat16 g_sl[NN * HD];                    // 4 MB (lo)
static __device__ __nv_bfloat16 g_simh[(size_t)NN * NN];          // 128 MB (bf16 filter sim)

// ---- packed f32x2 helpers (FFMA2 path, PTX-only) ---------------------------
__device__ __forceinline__ void fma2(u64 &d, u64 a, u64 b) {
    asm("fma.rn.f32x2 %0, %1, %2, %3;" : "=l"(d) : "l"(a), "l"(b), "l"(d));
}
__device__ __forceinline__ u64 dup2(float x) {
    u64 r; asm("mov.b64 %0, {%1, %1};" : "=l"(r) : "f"(x)); return r;
}
__device__ __forceinline__ void unpack2(u64 v, float &lo, float &hi) {
    asm("mov.b64 {%0, %1}, %2;" : "=f"(lo), "=f"(hi) : "l"(v));
}
__device__ __forceinline__ uint32_t smem_to_u32(const void* p) {
    uint32_t a;
    asm("{ .reg .u64 t; cvta.to.shared.u64 t, %1; cvt.u32.u64 %0, t; }" : "=r"(a) : "l"(p));
    return a;
}

// ---------------------------------------------------------------------------
// Output zero-fill (separate streaming kernel: HBM-rate, not inside topk).
// ---------------------------------------------------------------------------
__global__ void zerofill_kernel(float4* __restrict__ out, int n4)
{
    const int stride = gridDim.x * blockDim.x;
    float4 z = make_float4(0.f, 0.f, 0.f, 0.f);
    for (int i = blockIdx.x * blockDim.x + threadIdx.x; i < n4; i += stride)
        out[i] = z;
}

// ---------------------------------------------------------------------------
// Encoder (unchanged; per-element k-order frozen since R2).
// ---------------------------------------------------------------------------
__device__ __forceinline__ void enc_gemm_one(
    float (&total)[8][8],
    const float* __restrict__ X, const float* __restrict__ W,
    const float* __restrict__ bias,
    int K, int rowBase, int colBase, int tid,
    float (*As)[8][128], float (*Bs)[8][128])
{
    const int arow = tid >> 1;
    const int akx  = (tid & 1) * 4;
    const int bk   = tid >> 5;
    const int bn   = (tid & 31) * 4;
    const int ty   = tid >> 4;
    const int tx   = tid & 15;

    const float* aPtr = X + (size_t)(rowBase + arow) * K + akx;
    const float* bPtr = W + (size_t)bk * HD + colBase + bn;

    u64 acc2[4][8];
    #pragma unroll
    for (int i = 0; i < 4; i++)
        #pragma unroll
        for (int j = 0; j < 8; j++) acc2[i][j] = 0ULL;

    const int ntiles = K >> 3;

    float4 a4 = *(const float4*)aPtr;
    float4 b4 = *(const float4*)bPtr;
    As[0][akx + 0][arow] = a4.x; As[0][akx + 1][arow] = a4.y;
    As[0][akx + 2][arow] = a4.z; As[0][akx + 3][arow] = a4.w;
    *(float4*)&Bs[0][bk][bn] = b4;
    __syncthreads();

    for (int t = 0; t < ntiles; ++t) {
        const int cur = t & 1;
        if (t + 1 < ntiles) {
            a4 = *(const float4*)(aPtr + (t + 1) * 8);
            b4 = *(const float4*)(bPtr + (size_t)(t + 1) * 8 * HD);
        }
        #pragma unroll
        for (int kk = 0; kk < 8; kk++) {
            ulonglong2 a01 = *(const ulonglong2*)&As[cur][kk][ty * 8];
            ulonglong2 a23 = *(const ulonglong2*)&As[cur][kk][ty * 8 + 4];
            float4 B0 = *(const float4*)&Bs[cur][kk][tx * 8];
            float4 B1 = *(const float4*)&Bs[cur][kk][tx * 8 + 4];
            u64 brd[8];
            brd[0] = dup2(B0.x); brd[1] = dup2(B0.y);
            brd[2] = dup2(B0.z); brd[3] = dup2(B0.w);
            brd[4] = dup2(B1.x); brd[5] = dup2(B1.y);
            brd[6] = dup2(B1.z); brd[7] = dup2(B1.w);
            #pragma unroll
            for (int j = 0; j < 8; j++) {
                fma2(acc2[0][j], a01.x, brd[j]);
                fma2(acc2[1][j], a01.y, brd[j]);
                fma2(acc2[2][j], a23.x, brd[j]);
                fma2(acc2[3][j], a23.y, brd[j]);
            }
        }
        if (t + 1 < ntiles) {
            const int nxt = cur ^ 1;
            As[nxt][akx + 0][arow] = a4.x; As[nxt][akx + 1][arow] = a4.y;
            As[nxt][akx + 2][arow] = a4.z; As[nxt][akx + 3][arow] = a4.w;
            *(float4*)&Bs[nxt][bk][bn] = b4;
        }
        __syncthreads();
    }

    const int col = colBase + tx * 8;
    float bb[8];
    #pragma unroll
    for (int j = 0; j < 8; j++) bb[j] = bias[col + j];
    #pragma unroll
    for (int i2 = 0; i2 < 4; i2++)
        #pragma unroll
        for (int j = 0; j < 8; j++) {
            float lo, hi;
            unpack2(acc2[i2][j], lo, hi);
            total[2 * i2 + 0][j] += fmaxf(lo + bb[j], 0.0f);
            total[2 * i2 + 1][j] += fmaxf(hi + bb[j], 0.0f);
        }
}

__global__ __launch_bounds__(256, 1)
void enc_kernel(const float* __restrict__ X0, const float* __restrict__ W0, const float* __restrict__ b0,
                const float* __restrict__ X1, const float* __restrict__ W1, const float* __restrict__ b1,
                const float* __restrict__ X2, const float* __restrict__ W2, const float* __restrict__ b2)
{
    __shared__ __align__(16) float As[2][8][128];
    __shared__ __align__(16) float Bs[2][8][128];
    const int tid = threadIdx.x;
    const int rowBase = blockIdx.y * 128;
    const int colBase = blockIdx.x * 128;

    float total[8][8];
    #pragma unroll
    for (int i = 0; i < 8; i++)
        #pragma unroll
        for (int j = 0; j < 8; j++) total[i][j] = 0.0f;

    enc_gemm_one(total, X0, W0, b0, 1024, rowBase, colBase, tid, As, Bs);
    enc_gemm_one(total, X1, W1, b1,  768, rowBase, colBase, tid, As, Bs);
    enc_gemm_one(total, X2, W2, b2,  512, rowBase, colBase, tid, As, Bs);

    const int ty = tid >> 4, tx = tid & 15;
    const int row = rowBase + ty * 8;
    const int col = colBase + tx * 8;
    #pragma unroll
    for (int i = 0; i < 8; i++) {
        float4 o0 = make_float4(total[i][0], total[i][1], total[i][2], total[i][3]);
        float4 o1 = make_float4(total[i][4], total[i][5], total[i][6], total[i][7]);
        *(float4*)&g_fused[(size_t)(row + i) * HD + col]     = o0;
        *(float4*)&g_fused[(size_t)(row + i) * HD + col + 4] = o1;
    }
}

// ---------------------------------------------------------------------------
// Row normalize + fp32 hn + bf16x3 split (h + m + l). (unchanged)
// ---------------------------------------------------------------------------
__global__ void norm_kernel()
{
    const int tid  = threadIdx.x;
    const int lane = tid & 31;
    const int warp = tid >> 5;
    const int row  = blockIdx.x * 8 + warp;

    const float* fr = g_fused + (size_t)row * HD;
    float v[8];
    float ss = 0.0f;
    #pragma unroll
    for (int i = 0; i < 8; i++) {
        float x = fr[lane + i * 32] / 3.0f;
        v[i] = x;
        ss += x * x;
    }
    #pragma unroll
    for (int off = 16; off > 0; off >>= 1)
        ss += __shfl_xor_sync(0xffffffffu, ss, off);
    const float den = sqrtf(ss) + 1e-8f;
    #pragma unroll
    for (int i = 0; i < 8; i++) {
        const float x = v[i] / den;
        const size_t o = (size_t)row * HD + lane + i * 32;
        g_hn[o] = x;
        __nv_bfloat16 h = __float2bfloat16(x);
        float r1 = x - __bfloat162float(h);
        __nv_bfloat16 m = __float2bfloat16(r1);
        float r2 = r1 - __bfloat162float(m);
        __nv_bfloat16 l = __float2bfloat16(r2);
        g_sh[o] = h; g_sm[o] = m; g_sl[o] = l;
    }
}

// ---------------------------------------------------------------------------
// sim = hn @ hn^T via mma.sync.m16n8k16.bf16 (R13 inner loop), bf16x3 split,
// 6 products, fp32 accumulators. Output stored as bf16 (filter-only, halves
// traffic). FILTER PRECISION: bf16 round 0.002 + MMA ~2e-6.
// ---------------------------------------------------------------------------
#define KC 32
#define ROWB 80
#define TILE_BYTES (128 * ROWB)
#define SIM_SMEM (6 * TILE_BYTES)

__device__ __forceinline__ void ldsm_x4(uint32_t (&r)[4], uint32_t addr) {
    asm volatile("ldmatrix.sync.aligned.m8n8.x4.shared.b16 {%0,%1,%2,%3}, [%4];"
                 : "=r"(r[0]), "=r"(r[1]), "=r"(r[2]), "=r"(r[3]) : "r"(addr));
}
__device__ __forceinline__ void ldsm_x2(uint32_t (&r)[2], uint32_t addr) {
    asm volatile("ldmatrix.sync.aligned.m8n8.x2.shared.b16 {%0,%1}, [%2];"
                 : "=r"(r[0]), "=r"(r[1]) : "r"(addr));
}
__device__ __forceinline__ void mma_bf16(float (&d)[4], const uint32_t (&a)[4],
                                         const uint32_t (&b)[2]) {
    asm volatile("mma.sync.aligned.m16n8k16.row.col.f32.bf16.bf16.f32 "
                 "{%0,%1,%2,%3}, {%4,%5,%6,%7}, {%8,%9}, {%0,%1,%2,%3};"
                 : "+f"(d[0]), "+f"(d[1]), "+f"(d[2]), "+f"(d[3])
                 : "r"(a[0]), "r"(a[1]), "r"(a[2]), "r"(a[3]), "r"(b[0]), "r"(b[1]));
}

__global__ __launch_bounds__(256, 2)
void sim_mma_kernel()
{
    const int bx = blockIdx.x, by = blockIdx.y;
    if (by > bx) return;

    extern __shared__ __align__(16) char smem[];
    const uint32_t sbase = smem_to_u32(smem);
    const int tid   = threadIdx.x;
    const int lane  = tid & 31;
    const int wid   = tid >> 5;
    const int warpM = wid & 1;
    const int warpN = wid >> 1;
    const int rowBase = by * 128;
    const int colBase = bx * 128;

    const __nv_bfloat16* srcs[6] = {g_sh, g_sm, g_sl, g_sh, g_sm, g_sl};

    float acc[4][4][4];
    #pragma unroll
    for (int mt = 0; mt < 4; mt++)
        #pragma unroll
        for (int nt = 0; nt < 4; nt++)
            #pragma unroll
            for (int r = 0; r < 4; r++) acc[mt][nt][r] = 0.0f;

    const uint32_t aBase = (uint32_t)((warpM * 64 + (lane & 15)) * ROWB + (lane >> 4) * 16);
    const uint32_t bBase = (uint32_t)((warpN * 32 + (lane & 7)) * ROWB + ((lane >> 3) & 1) * 16);

    for (int ch = 0; ch < 8; ++ch) {
        const int ko = ch * KC;
        #pragma unroll
        for (int t = 0; t < 6; ++t) {
            const int rb = (t < 3) ? rowBase : colBase;
            const __nv_bfloat16* src = srcs[t];
            #pragma unroll
            for (int q = 0; q < 2; ++q) {
                const int idx = q * 256 + tid;
                const int r = idx >> 2;
                const int c = (idx & 3) * 8;
                uint4 val = *(const uint4*)&src[(size_t)(rb + r) * HD + ko + c];
                *(uint4*)(smem + t * TILE_BYTES + r * ROWB + c * 2) = val;
            }
        }
        __syncthreads();

        #pragma unroll
        for (int ks = 0; ks < 2; ++ks) {
            const uint32_t kb = (uint32_t)(ks * 32);
            #pragma unroll
            for (int as = 0; as < 3; ++as) {
                uint32_t afrag[4][4];
                #pragma unroll
                for (int mt = 0; mt < 4; mt++)
                    ldsm_x4(afrag[mt], sbase + as * TILE_BYTES + aBase + mt * 16 * ROWB + kb);
                const int nb = (as == 0) ? 3 : ((as == 1) ? 2 : 1);
                for (int bs = 0; bs < nb; ++bs) {
                    #pragma unroll
                    for (int nt = 0; nt < 4; nt++) {
                        uint32_t bfrag[2];
                        ldsm_x2(bfrag, sbase + (3 + bs) * TILE_BYTES + bBase + nt * 8 * ROWB + kb);
                        #pragma unroll
                        for (int mt = 0; mt < 4; mt++)
                            mma_bf16(acc[mt][nt], afrag[mt], bfrag);
                    }
                }
            }
        }
        __syncthreads();
    }

    const int r0 = lane >> 2;
    const int c0 = (lane & 3) * 2;
    #pragma unroll
    for (int mt = 0; mt < 4; mt++) {
        #pragma unroll
        for (int nt = 0; nt < 4; nt++) {
            const int rg = rowBase + warpM * 64 + mt * 16 + r0;
            const int cg = colBase + warpN * 32 + nt * 8 + c0;
            __nv_bfloat16 b0 = __float2bfloat16(acc[mt][nt][0]);
            __nv_bfloat16 b1 = __float2bfloat16(acc[mt][nt][1]);
            __nv_bfloat16 b2 = __float2bfloat16(acc[mt][nt][2]);
            __nv_bfloat16 b3 = __float2bfloat16(acc[mt][nt][3]);
            __nv_bfloat162 p01; p01.x = b0; p01.y = b1;
            __nv_bfloat162 p23; p23.x = b2; p23.y = b3;
            *(__nv_bfloat162*)&g_simh[(size_t)rg * NN + cg]       = p01;
            *(__nv_bfloat162*)&g_simh[(size_t)(rg + 8) * NN + cg] = p23;
            if (by != bx) {
                g_simh[(size_t)cg * NN + rg]           = b0;
                g_simh[(size_t)(cg + 1) * NN + rg]     = b1;
                g_simh[(size_t)cg * NN + rg + 8]       = b2;
                g_simh[(size_t)(cg + 1) * NN + rg + 8] = b3;
            }
        }
    }
}

// ---------------------------------------------------------------------------
// Top-16 per row (R13 structure, bf16 source, widened margins, no zero-fill):
//  (1) histogram on bf16 sim -> b1; cut = bin_lo(b1) - 0.0045
//      (bf16 round 0.002 x2 + MMA eps; provable superset)
//  (2) approx destructive top-16 -> t16; rescore set = winners + candidates
//      with bf16 value >= t16 - 0.005
//  (3) exact sequential-k fp32 rescore (R1-R3-identical chain) + exact top-16
// ---------------------------------------------------------------------------
__device__ __forceinline__ float key_val(u64 k) {
    unsigned u = (unsigned)(k >> 32);
    unsigned s = (u & 0x80000000u) ? (u ^ 0x80000000u) : ~u;
    return __uint_as_float(s);
}
__device__ __forceinline__ int bin_of(float v) {
    int b = (int)((v + 1.0f) * 128.0f);
    return max(0, min(255, b));
}

#define CAND_CAP 3072
#define RESC_CAP 512

__global__ __launch_bounds__(256)
void topk_kernel(float* __restrict__ out)
{
    const int row  = blockIdx.x;
    const int tid  = threadIdx.x;
    const int lane = tid & 31;
    const int wid  = tid >> 5;

    __shared__ unsigned hist[256];
    __shared__ int s_b1;
    __shared__ unsigned candCnt;
    __shared__ u64  candKey[CAND_CAP];
    __shared__ float rowVec[HD];
    __shared__ u64  sFinal[16];
    __shared__ int  rescIdx[RESC_CAP];
    __shared__ u64  rescKey[RESC_CAP];
    __shared__ unsigned rescCnt;
    __shared__ float s_keep;

    hist[tid] = 0u;
    if (tid == 0) { candCnt = 0u; rescCnt = 16u; }
    rowVec[tid] = g_hn[(size_t)row * HD + tid];
    __syncthreads();

    // load bf16 sim row as bf16x2 (16 x u32 per thread), diag -> -2
    float v[32];
    const __nv_bfloat162* srow2 = (const __nv_bfloat162*)(g_simh + (size_t)row * NN);
    #pragma unroll
    for (int j = 0; j < 16; j++) {
        const int c2 = tid + j * 256;          // pair index: cols 2*c2, 2*c2+1
        __nv_bfloat162 p = srow2[c2];
        float x0 = __bfloat162float(p.x);
        float x1 = __bfloat162float(p.y);
        v[2 * j]     = (2 * c2 == row)     ? -2.0f : x0;
        v[2 * j + 1] = (2 * c2 + 1 == row) ? -2.0f : x1;
    }

    #pragma unroll
    for (int j = 0; j < 32; j++)
        atomicAdd(&hist[bin_of(v[j])], 1u);
    __syncthreads();

    // warp 0: b1 = max bin with suffix count >= 16
    if (wid == 0) {
        unsigned h[8];
        unsigned s = 0;
        #pragma unroll
        for (int q = 0; q < 8; q++) { h[q] = hist[lane * 8 + q]; s += h[q]; }
        unsigned suf = s;
        #pragma unroll
        for (int off = 1; off < 32; off <<= 1) {
            unsigned o = __shfl_down_sync(0xffffffffu, suf, off);
            if (lane + off < 32) suf += o;
        }
        unsigned run = suf - s;
        int best = -1;
        #pragma unroll
        for (int q = 7; q >= 0; q--) {
            run += h[q];
            if (best < 0 && run >= 16u) best = lane * 8 + q;
        }
        #pragma unroll
        for (int off = 16; off > 0; off >>= 1) {
            int o = __shfl_xor_sync(0xffffffffu, best, off);
            best = max(best, o);
        }
        if (lane == 0) s_b1 = best;
    }
    __syncthreads();
    // margin: 2x bf16 rounding (0.002 each) + MMA eps
    const float cutLo = (float)s_b1 / 128.0f - 1.0f - 0.0045f;

    // collect approx candidate keys, warp-aggregated append
    #pragma unroll
    for (int j = 0; j < 32; j++) {
        const bool p = (v[j] >= cutLo);
        const unsigned m = __ballot_sync(0xffffffffu, p);
        if (m == 0u) continue;
        const int leader = __ffs(m) - 1;
        unsigned base = 0;
        if (lane == leader) base = atomicAdd(&candCnt, (unsigned)__popc(m));
        base = __shfl_sync(0xffffffffu, base, leader);
        if (p) {
            const unsigned pos = base + __popc(m & ((1u << lane) - 1u));
            if (pos < CAND_CAP) {
                const int c = 2 * (tid + (j >> 1) * 256) + (j & 1);
                unsigned sb = __float_as_uint(v[j]);
                unsigned u = sb ^ ((unsigned)((int)sb >> 31) | 0x80000000u);
                candKey[pos] = ((u64)u << 32) | (unsigned)(~c);
            }
        }
    }
    __syncthreads();

    const int n = min((int)candCnt, CAND_CAP);

    // warp 0: approx top-16 (destructive) -> t16
    if (wid == 0) {
        for (int it = 0; it < 16; ++it) {
            u64 lm = 0ULL;
            for (int i = lane; i < n; i += 32) {
                u64 k = candKey[i];
                if (k > lm) lm = k;
            }
            u64 w = lm;
            #pragma unroll
            for (int off = 16; off > 0; off >>= 1) {
                u64 o = __shfl_xor_sync(0xffffffffu, w, off);
                if (o > w) w = o;
            }
            if (lane == 0) sFinal[it] = w;
            for (int i = lane; i < n; i += 32)
                if (candKey[i] == w) candKey[i] = 0ULL;
        }
    }
    __syncthreads();

    // rescore set: 16 approx winners + extras with bf16 value >= t16 - 0.005
    if (tid < 16) rescIdx[tid] = (int)(~(unsigned)(sFinal[tid] & 0xffffffffu));
    const float thr = key_val(sFinal[15]) - 0.005f;
    for (int i = tid; i < n; i += 256) {
        const u64 k = candKey[i];
        if (k != 0ULL && key_val(k) >= thr) {
            const unsigned pos = atomicAdd(&rescCnt, 1u);
            if (pos < RESC_CAP) rescIdx[pos] = (int)(~(unsigned)(k & 0xffffffffu));
        }
    }
    __syncthreads();

    const int m = min((int)rescCnt, RESC_CAP);

    // exact rescore: one thread per candidate, sequential k=0..255 fmaf chain
    // (bitwise identical to the R1-R3 passing sim computation).
    for (int i = tid; i < m; i += 256) {
        const int c = rescIdx[i];
        const float4* cv4 = (const float4*)(g_hn + (size_t)c * HD);
        float acc = 0.0f;
        #pragma unroll 4
        for (int k4 = 0; k4 < HD / 4; k4++) {
            float4 b = cv4[k4];
            acc = fmaf(rowVec[4 * k4 + 0], b.x, acc);
            acc = fmaf(rowVec[4 * k4 + 1], b.y, acc);
            acc = fmaf(rowVec[4 * k4 + 2], b.z, acc);
            acc = fmaf(rowVec[4 * k4 + 3], b.w, acc);
        }
        unsigned sb = __float_as_uint(acc);
        unsigned u = sb ^ ((unsigned)((int)sb >> 31) | 0x80000000u);
        rescKey[i] = ((u64)u << 32) | (unsigned)(~c);
    }
    __syncthreads();

    // warp 0: exact top-16 over m rescored candidates
    if (wid == 0) {
        for (int it = 0; it < 16; ++it) {
            u64 lm = 0ULL;
            for (int i = lane; i < m; i += 32) {
                u64 k = rescKey[i];
                if (k > lm) lm = k;
            }
            u64 w = lm;
            #pragma unroll
            for (int off = 16; off > 0; off >>= 1) {
                u64 o = __shfl_xor_sync(0xffffffffu, w, off);
                if (o > w) w = o;
            }
            if (lane == 0) sFinal[it] = w;
            for (int i = lane; i < m; i += 32)
                if (rescKey[i] == w) rescKey[i] = 0ULL;
        }
        if (lane == 0) {
            float sum = 0.0f;
            #pragma unroll
            for (int it = 0; it < 16; ++it) sum += key_val(sFinal[it]);
            s_keep = (sum / 16.0f > 0.5f) ? 1.0f : 0.0f;
        }
    }
    __syncthreads();

    if (tid < 16) {
        const u64 k = sFinal[tid];
        const int c = (int)(~(unsigned)(k & 0xffffffffu));
        out[(size_t)row * NN + c] = key_val(k) * s_keep;
    }
}

// ---------------------------------------------------------------------------
extern "C" void kernel_launch(void* const* d_in, const int* in_sizes, int n_in,
                              void* d_out, int out_size)
{
    const float* x_img = (const float*)d_in[0];
    const float* W_img = (const float*)d_in[1];
    const float* b_img = (const float*)d_in[2];
    const float* x_txt = (const float*)d_in[3];
    const float* W_txt = (const float*)d_in[4];
    const float* b_txt = (const float*)d_in[5];
    const float* x_aud = (const float*)d_in[6];
    const float* W_aud = (const float*)d_in[7];
    const float* b_aud = (const float*)d_in[8];
    float* out = (float*)d_out;

    cudaFuncSetAttribute(sim_mma_kernel, cudaFuncAttributeMaxDynamicSharedMemorySize, SIM_SMEM);

    zerofill_kernel<<<4096, 256>>>((float4*)out, (int)((size_t)NN * NN / 4));
    enc_kernel<<<dim3(2, 64), 256>>>(x_img, W_img, b_img,
                                     x_txt, W_txt, b_txt,
                                     x_aud, W_aud, b_aud);
    norm_kernel<<<1024, 256>>>();
    sim_mma_kernel<<<dim3(64, 64), 256, SIM_SMEM>>>();
    topk_kernel<<<NN, 256>>>(out);
}

// round 16
// speedup vs baseline: 1.1917x; 1.1436x over previous
#include <cuda_runtime.h>
#include <cuda_bf16.h>
#include <math.h>
#include <cstdint>

#define NN 8192
#define HD 256

typedef unsigned long long u64;

// Scratch (device globals: allocation-free rule).
static __device__ float g_fused[NN * HD];                         // 8 MB
static __device__ float g_hn[NN * HD];                            // 8 MB (fp32, for rescore)
static __device__ __nv_bfloat16 g_sh[NN * HD];                    // 4 MB (hi)
static __device__ __nv_bfloat16 g_sm[NN * HD];                    // 4 MB (mid)
static __device__ __nv_bfloat16 g_simh[(size_t)NN * NN];          // 128 MB (bf16 filter sim)

// ---- packed f32x2 helpers (FFMA2 path, PTX-only) ---------------------------
__device__ __forceinline__ void fma2(u64 &d, u64 a, u64 b) {
    asm("fma.rn.f32x2 %0, %1, %2, %3;" : "=l"(d) : "l"(a), "l"(b), "l"(d));
}
__device__ __forceinline__ u64 dup2(float x) {
    u64 r; asm("mov.b64 %0, {%1, %1};" : "=l"(r) : "f"(x)); return r;
}
__device__ __forceinline__ void unpack2(u64 v, float &lo, float &hi) {
    asm("mov.b64 {%0, %1}, %2;" : "=f"(lo), "=f"(hi) : "l"(v));
}
__device__ __forceinline__ uint32_t smem_to_u32(const void* p) {
    uint32_t a;
    asm("{ .reg .u64 t; cvta.to.shared.u64 t, %1; cvt.u32.u64 %0, t; }" : "=r"(a) : "l"(p));
    return a;
}

// ---------------------------------------------------------------------------
// Encoder (unchanged; per-element k-order frozen since R2).
// ---------------------------------------------------------------------------
__device__ __forceinline__ void enc_gemm_one(
    float (&total)[8][8],
    const float* __restrict__ X, const float* __restrict__ W,
    const float* __restrict__ bias,
    int K, int rowBase, int colBase, int tid,
    float (*As)[8][128], float (*Bs)[8][128])
{
    const int arow = tid >> 1;
    const int akx  = (tid & 1) * 4;
    const int bk   = tid >> 5;
    const int bn   = (tid & 31) * 4;
    const int ty   = tid >> 4;
    const int tx   = tid & 15;

    const float* aPtr = X + (size_t)(rowBase + arow) * K + akx;
    const float* bPtr = W + (size_t)bk * HD + colBase + bn;

    u64 acc2[4][8];
    #pragma unroll
    for (int i = 0; i < 4; i++)
        #pragma unroll
        for (int j = 0; j < 8; j++) acc2[i][j] = 0ULL;

    const int ntiles = K >> 3;

    float4 a4 = *(const float4*)aPtr;
    float4 b4 = *(const float4*)bPtr;
    As[0][akx + 0][arow] = a4.x; As[0][akx + 1][arow] = a4.y;
    As[0][akx + 2][arow] = a4.z; As[0][akx + 3][arow] = a4.w;
    *(float4*)&Bs[0][bk][bn] = b4;
    __syncthreads();

    for (int t = 0; t < ntiles; ++t) {
        const int cur = t & 1;
        if (t + 1 < ntiles) {
            a4 = *(const float4*)(aPtr + (t + 1) * 8);
            b4 = *(const float4*)(bPtr + (size_t)(t + 1) * 8 * HD);
        }
        #pragma unroll
        for (int kk = 0; kk < 8; kk++) {
            ulonglong2 a01 = *(const ulonglong2*)&As[cur][kk][ty * 8];
            ulonglong2 a23 = *(const ulonglong2*)&As[cur][kk][ty * 8 + 4];
            float4 B0 = *(const float4*)&Bs[cur][kk][tx * 8];
            float4 B1 = *(const float4*)&Bs[cur][kk][tx * 8 + 4];
            u64 brd[8];
            brd[0] = dup2(B0.x); brd[1] = dup2(B0.y);
            brd[2] = dup2(B0.z); brd[3] = dup2(B0.w);
            brd[4] = dup2(B1.x); brd[5] = dup2(B1.y);
            brd[6] = dup2(B1.z); brd[7] = dup2(B1.w);
            #pragma unroll
            for (int j = 0; j < 8; j++) {
                fma2(acc2[0][j], a01.x, brd[j]);
                fma2(acc2[1][j], a01.y, brd[j]);
                fma2(acc2[2][j], a23.x, brd[j]);
                fma2(acc2[3][j], a23.y, brd[j]);
            }
        }
        if (t + 1 < ntiles) {
            const int nxt = cur ^ 1;
            As[nxt][akx + 0][arow] = a4.x; As[nxt][akx + 1][arow] = a4.y;
            As[nxt][akx + 2][arow] = a4.z; As[nxt][akx + 3][arow] = a4.w;
            *(float4*)&Bs[nxt][bk][bn] = b4;
        }
        __syncthreads();
    }

    const int col = colBase + tx * 8;
    float bb[8];
    #pragma unroll
    for (int j = 0; j < 8; j++) bb[j] = bias[col + j];
    #pragma unroll
    for (int i2 = 0; i2 < 4; i2++)
        #pragma unroll
        for (int j = 0; j < 8; j++) {
            float lo, hi;
            unpack2(acc2[i2][j], lo, hi);
            total[2 * i2 + 0][j] += fmaxf(lo + bb[j], 0.0f);
            total[2 * i2 + 1][j] += fmaxf(hi + bb[j], 0.0f);
        }
}

__global__ __launch_bounds__(256, 1)
void enc_kernel(const float* __restrict__ X0, const float* __restrict__ W0, const float* __restrict__ b0,
                const float* __restrict__ X1, const float* __restrict__ W1, const float* __restrict__ b1,
                const float* __restrict__ X2, const float* __restrict__ W2, const float* __restrict__ b2)
{
    __shared__ __align__(16) float As[2][8][128];
    __shared__ __align__(16) float Bs[2][8][128];
    const int tid = threadIdx.x;
    const int rowBase = blockIdx.y * 128;
    const int colBase = blockIdx.x * 128;

    float total[8][8];
    #pragma unroll
    for (int i = 0; i < 8; i++)
        #pragma unroll
        for (int j = 0; j < 8; j++) total[i][j] = 0.0f;

    enc_gemm_one(total, X0, W0, b0, 1024, rowBase, colBase, tid, As, Bs);
    enc_gemm_one(total, X1, W1, b1,  768, rowBase, colBase, tid, As, Bs);
    enc_gemm_one(total, X2, W2, b2,  512, rowBase, colBase, tid, As, Bs);

    const int ty = tid >> 4, tx = tid & 15;
    const int row = rowBase + ty * 8;
    const int col = colBase + tx * 8;
    #pragma unroll
    for (int i = 0; i < 8; i++) {
        float4 o0 = make_float4(total[i][0], total[i][1], total[i][2], total[i][3]);
        float4 o1 = make_float4(total[i][4], total[i][5], total[i][6], total[i][7]);
        *(float4*)&g_fused[(size_t)(row + i) * HD + col]     = o0;
        *(float4*)&g_fused[(size_t)(row + i) * HD + col + 4] = o1;
    }
}

// ---------------------------------------------------------------------------
// Row normalize + fp32 hn + bf16x2 split (h + m; l no longer needed).
// ---------------------------------------------------------------------------
__global__ void norm_kernel()
{
    const int tid  = threadIdx.x;
    const int lane = tid & 31;
    const int warp = tid >> 5;
    const int row  = blockIdx.x * 8 + warp;

    const float* fr = g_fused + (size_t)row * HD;
    float v[8];
    float ss = 0.0f;
    #pragma unroll
    for (int i = 0; i < 8; i++) {
        float x = fr[lane + i * 32] / 3.0f;
        v[i] = x;
        ss += x * x;
    }
    #pragma unroll
    for (int off = 16; off > 0; off >>= 1)
        ss += __shfl_xor_sync(0xffffffffu, ss, off);
    const float den = sqrtf(ss) + 1e-8f;
    #pragma unroll
    for (int i = 0; i < 8; i++) {
        const float x = v[i] / den;
        const size_t o = (size_t)row * HD + lane + i * 32;
        g_hn[o] = x;
        __nv_bfloat16 h = __float2bfloat16(x);
        float r1 = x - __bfloat162float(h);
        __nv_bfloat16 m = __float2bfloat16(r1);
        g_sh[o] = h; g_sm[o] = m;
    }
}

// ---------------------------------------------------------------------------
// sim = hn @ hn^T via mma.sync.m16n8k16.bf16, bf16x2 split, 3 products
// (hh + hm + mh; dropped hl/lh/mm contribute <= ~1e-5, far below the 0.0045
// filter margin). fp32 accumulators, bf16 output. The by>bx early-return CTAs
// zero-fill the output buffer (DRAM idle in this kernel; removes the
// dedicated zerofill launch).
// ---------------------------------------------------------------------------
#define KC 32
#define ROWB 80
#define TILE_BYTES (128 * ROWB)
#define SIM_SMEM (4 * TILE_BYTES)

__device__ __forceinline__ void ldsm_x4(uint32_t (&r)[4], uint32_t addr) {
    asm volatile("ldmatrix.sync.aligned.m8n8.x4.shared.b16 {%0,%1,%2,%3}, [%4];"
                 : "=r"(r[0]), "=r"(r[1]), "=r"(r[2]), "=r"(r[3]) : "r"(addr));
}
__device__ __forceinline__ void ldsm_x2(uint32_t (&r)[2], uint32_t addr) {
    asm volatile("ldmatrix.sync.aligned.m8n8.x2.shared.b16 {%0,%1}, [%2];"
                 : "=r"(r[0]), "=r"(r[1]) : "r"(addr));
}
__device__ __forceinline__ void mma_bf16(float (&d)[4], const uint32_t (&a)[4],
                                         const uint32_t (&b)[2]) {
    asm volatile("mma.sync.aligned.m16n8k16.row.col.f32.bf16.bf16.f32 "
                 "{%0,%1,%2,%3}, {%4,%5,%6,%7}, {%8,%9}, {%0,%1,%2,%3};"
                 : "+f"(d[0]), "+f"(d[1]), "+f"(d[2]), "+f"(d[3])
                 : "r"(a[0]), "r"(a[1]), "r"(a[2]), "r"(a[3]), "r"(b[0]), "r"(b[1]));
}

__global__ __launch_bounds__(256, 2)
void sim_mma_kernel(float* __restrict__ out)
{
    const int bx = blockIdx.x, by = blockIdx.y;
    const int tid = threadIdx.x;

    if (by > bx) {
        // zero-fill worker: rank r in 0..2015, slice of out (16M float4 total)
        const int r = by * (by - 1) / 2 + bx;
        const size_t total4 = (size_t)NN * NN / 4;
        const size_t per = (total4 + 2015) / 2016;
        size_t beg = (size_t)r * per;
        size_t end = beg + per; if (end > total4) end = total4;
        float4 z = make_float4(0.f, 0.f, 0.f, 0.f);
        float4* o4 = (float4*)out;
        for (size_t i = beg + tid; i < end; i += 256) o4[i] = z;
        return;
    }

    extern __shared__ __align__(16) char smem[];
    const uint32_t sbase = smem_to_u32(smem);
    const int lane  = tid & 31;
    const int wid   = tid >> 5;
    const int warpM = wid & 1;
    const int warpN = wid >> 1;
    const int rowBase = by * 128;
    const int colBase = bx * 128;

    // tiles: 0 = row-h, 1 = row-m, 2 = col-h, 3 = col-m
    const __nv_bfloat16* srcs[4] = {g_sh, g_sm, g_sh, g_sm};

    float acc[4][4][4];
    #pragma unroll
    for (int mt = 0; mt < 4; mt++)
        #pragma unroll
        for (int nt = 0; nt < 4; nt++)
            #pragma unroll
            for (int r = 0; r < 4; r++) acc[mt][nt][r] = 0.0f;

    const uint32_t aBase = (uint32_t)((warpM * 64 + (lane & 15)) * ROWB + (lane >> 4) * 16);
    const uint32_t bBase = (uint32_t)((warpN * 32 + (lane & 7)) * ROWB + ((lane >> 3) & 1) * 16);

    for (int ch = 0; ch < 8; ++ch) {
        const int ko = ch * KC;
        #pragma unroll
        for (int t = 0; t < 4; ++t) {
            const int rb = (t < 2) ? rowBase : colBase;
            const __nv_bfloat16* src = srcs[t];
            #pragma unroll
            for (int q = 0; q < 2; ++q) {
                const int idx = q * 256 + tid;
                const int r = idx >> 2;
                const int c = (idx & 3) * 8;
                uint4 val = *(const uint4*)&src[(size_t)(rb + r) * HD + ko + c];
                *(uint4*)(smem + t * TILE_BYTES + r * ROWB + c * 2) = val;
            }
        }
        __syncthreads();

        #pragma unroll
        for (int ks = 0; ks < 2; ++ks) {
            const uint32_t kb = (uint32_t)(ks * 32);
            #pragma unroll
            for (int as = 0; as < 2; ++as) {        // 0 = h-rows, 1 = m-rows
                uint32_t afrag[4][4];
                #pragma unroll
                for (int mt = 0; mt < 4; mt++)
                    ldsm_x4(afrag[mt], sbase + as * TILE_BYTES + aBase + mt * 16 * ROWB + kb);
                const int nb = (as == 0) ? 2 : 1;   // hh+hm, then mh
                for (int bs = 0; bs < nb; ++bs) {
                    #pragma unroll
                    for (int nt = 0; nt < 4; nt++) {
                        uint32_t bfrag[2];
                        ldsm_x2(bfrag, sbase + (2 + bs) * TILE_BYTES + bBase + nt * 8 * ROWB + kb);
                        #pragma unroll
                        for (int mt = 0; mt < 4; mt++)
                            mma_bf16(acc[mt][nt], afrag[mt], bfrag);
                    }
                }
            }
        }
        __syncthreads();
    }

    const int r0 = lane >> 2;
    const int c0 = (lane & 3) * 2;
    #pragma unroll
    for (int mt = 0; mt < 4; mt++) {
        #pragma unroll
        for (int nt = 0; nt < 4; nt++) {
            const int rg = rowBase + warpM * 64 + mt * 16 + r0;
            const int cg = colBase + warpN * 32 + nt * 8 + c0;
            __nv_bfloat16 b0 = __float2bfloat16(acc[mt][nt][0]);
            __nv_bfloat16 b1 = __float2bfloat16(acc[mt][nt][1]);
            __nv_bfloat16 b2 = __float2bfloat16(acc[mt][nt][2]);
            __nv_bfloat16 b3 = __float2bfloat16(acc[mt][nt][3]);
            __nv_bfloat162 p01; p01.x = b0; p01.y = b1;
            __nv_bfloat162 p23; p23.x = b2; p23.y = b3;
            *(__nv_bfloat162*)&g_simh[(size_t)rg * NN + cg]       = p01;
            *(__nv_bfloat162*)&g_simh[(size_t)(rg + 8) * NN + cg] = p23;
            if (by != bx) {
                g_simh[(size_t)cg * NN + rg]           = b0;
                g_simh[(size_t)(cg + 1) * NN + rg]     = b1;
                g_simh[(size_t)cg * NN + rg + 8]       = b2;
                g_simh[(size_t)(cg + 1) * NN + rg + 8] = b3;
            }
        }
    }
}

// ---------------------------------------------------------------------------
// Top-16 per row (R15 structure, slimmer smem):
//  (1) histogram on bf16 sim -> b1; cut = bin_lo(b1) - 0.0045 (bf16 round
//      0.001 x2 + dropped-terms ~1e-5 + MMA eps; provable superset)
//  (2) approx destructive top-16 -> t16; rescore set = winners + candidates
//      with bf16 value >= t16 - 0.005
//  (3) exact sequential-k fp32 rescore (R1-R3-identical chain) + exact top-16
// ---------------------------------------------------------------------------
__device__ __forceinline__ float key_val(u64 k) {
    unsigned u = (unsigned)(k >> 32);
    unsigned s = (u & 0x80000000u) ? (u ^ 0x80000000u) : ~u;
    return __uint_as_float(s);
}
__device__ __forceinline__ int bin_of(float v) {
    int b = (int)((v + 1.0f) * 128.0f);
    return max(0, min(255, b));
}

#define CAND_CAP 2048
#define RESC_CAP 256

__global__ __launch_bounds__(256)
void topk_kernel(float* __restrict__ out)
{
    const int row  = blockIdx.x;
    const int tid  = threadIdx.x;
    const int lane = tid & 31;
    const int wid  = tid >> 5;

    __shared__ unsigned hist[256];
    __shared__ int s_b1;
    __shared__ unsigned candCnt;
    __shared__ u64  candKey[CAND_CAP];
    __shared__ float rowVec[HD];
    __shared__ u64  sFinal[16];
    __shared__ int  rescIdx[RESC_CAP];
    __shared__ u64  rescKey[RESC_CAP];
    __shared__ unsigned rescCnt;
    __shared__ float s_keep;

    hist[tid] = 0u;
    if (tid == 0) { candCnt = 0u; rescCnt = 16u; }
    rowVec[tid] = g_hn[(size_t)row * HD + tid];
    __syncthreads();

    // load bf16 sim row as bf16x2 (16 x u32 per thread), diag -> -2
    float v[32];
    const __nv_bfloat162* srow2 = (const __nv_bfloat162*)(g_simh + (size_t)row * NN);
    #pragma unroll
    for (int j = 0; j < 16; j++) {
        const int c2 = tid + j * 256;
        __nv_bfloat162 p = srow2[c2];
        float x0 = __bfloat162float(p.x);
        float x1 = __bfloat162float(p.y);
        v[2 * j]     = (2 * c2 == row)     ? -2.0f : x0;
        v[2 * j + 1] = (2 * c2 + 1 == row) ? -2.0f : x1;
    }

    #pragma unroll
    for (int j = 0; j < 32; j++)
        atomicAdd(&hist[bin_of(v[j])], 1u);
    __syncthreads();

    // warp 0: b1 = max bin with suffix count >= 16
    if (wid == 0) {
        unsigned h[8];
        unsigned s = 0;
        #pragma unroll
        for (int q = 0; q < 8; q++) { h[q] = hist[lane * 8 + q]; s += h[q]; }
        unsigned suf = s;
        #pragma unroll
        for (int off = 1; off < 32; off <<= 1) {
            unsigned o = __shfl_down_sync(0xffffffffu, suf, off);
            if (lane + off < 32) suf += o;
        }
        unsigned run = suf - s;
        int best = -1;
        #pragma unroll
        for (int q = 7; q >= 0; q--) {
            run += h[q];
            if (best < 0 && run >= 16u) best = lane * 8 + q;
        }
        #pragma unroll
        for (int off = 16; off > 0; off >>= 1) {
            int o = __shfl_xor_sync(0xffffffffu, best, off);
            best = max(best, o);
        }
        if (lane == 0) s_b1 = best;
    }
    __syncthreads();
    const float cutLo = (float)s_b1 / 128.0f - 1.0f - 0.0045f;

    // collect approx candidate keys, warp-aggregated append
    #pragma unroll
    for (int j = 0; j < 32; j++) {
        const bool p = (v[j] >= cutLo);
        const unsigned m = __ballot_sync(0xffffffffu, p);
        if (m == 0u) continue;
        const int leader = __ffs(m) - 1;
        unsigned base = 0;
        if (lane == leader) base = atomicAdd(&candCnt, (unsigned)__popc(m));
        base = __shfl_sync(0xffffffffu, base, leader);
        if (p) {
            const unsigned pos = base + __popc(m & ((1u << lane) - 1u));
            if (pos < CAND_CAP) {
                const int c = 2 * (tid + (j >> 1) * 256) + (j & 1);
                unsigned sb = __float_as_uint(v[j]);
                unsigned u = sb ^ ((unsigned)((int)sb >> 31) | 0x80000000u);
                candKey[pos] = ((u64)u << 32) | (unsigned)(~c);
            }
        }
    }
    __syncthreads();

    const int n = min((int)candCnt, CAND_CAP);

    // warp 0: approx top-16 (destructive) -> t16
    if (wid == 0) {
        for (int it = 0; it < 16; ++it) {
            u64 lm = 0ULL;
            for (int i = lane; i < n; i += 32) {
                u64 k = candKey[i];
                if (k > lm) lm = k;
            }
            u64 w = lm;
            #pragma unroll
            for (int off = 16; off > 0; off >>= 1) {
                u64 o = __shfl_xor_sync(0xffffffffu, w, off);
                if (o > w) w = o;
            }
            if (lane == 0) sFinal[it] = w;
            for (int i = lane; i < n; i += 32)
                if (candKey[i] == w) candKey[i] = 0ULL;
        }
    }
    __syncthreads();

    // rescore set: 16 approx winners + extras with bf16 value >= t16 - 0.005
    if (tid < 16) rescIdx[tid] = (int)(~(unsigned)(sFinal[tid] & 0xffffffffu));
    const float thr = key_val(sFinal[15]) - 0.005f;
    for (int i = tid; i < n; i += 256) {
        const u64 k = candKey[i];
        if (k != 0ULL && key_val(k) >= thr) {
            const unsigned pos = atomicAdd(&rescCnt, 1u);
            if (pos < RESC_CAP) rescIdx[pos] = (int)(~(unsigned)(k & 0xffffffffu));
        }
    }
    __syncthreads();

    const int m = min((int)rescCnt, RESC_CAP);

    // exact rescore: one thread per candidate, sequential k=0..255 fmaf chain
    // (bitwise identical to the R1-R3 passing sim computation).
    for (int i = tid; i < m; i += 256) {
        const int c = rescIdx[i];
        const float4* cv4 = (const float4*)(g_hn + (size_t)c * HD);
        float acc = 0.0f;
        #pragma unroll 4
        for (int k4 = 0; k4 < HD / 4; k4++) {
            float4 b = cv4[k4];
            acc = fmaf(rowVec[4 * k4 + 0], b.x, acc);
            acc = fmaf(rowVec[4 * k4 + 1], b.y, acc);
            acc = fmaf(rowVec[4 * k4 + 2], b.z, acc);
            acc = fmaf(rowVec[4 * k4 + 3], b.w, acc);
        }
        unsigned sb = __float_as_uint(acc);
        unsigned u = sb ^ ((unsigned)((int)sb >> 31) | 0x80000000u);
        rescKey[i] = ((u64)u << 32) | (unsigned)(~c);
    }
    __syncthreads();

    // warp 0: exact top-16 over m rescored candidates
    if (wid == 0) {
        for (int it = 0; it < 16; ++it) {
            u64 lm = 0ULL;
            for (int i = lane; i < m; i += 32) {
                u64 k = rescKey[i];
                if (k > lm) lm = k;
            }
            u64 w = lm;
            #pragma unroll
            for (int off = 16; off > 0; off >>= 1) {
                u64 o = __shfl_xor_sync(0xffffffffu, w, off);
                if (o > w) w = o;
            }
            if (lane == 0) sFinal[it] = w;
            for (int i = lane; i < m; i += 32)
                if (rescKey[i] == w) rescKey[i] = 0ULL;
        }
        if (lane == 0) {
            float sum = 0.0f;
            #pragma unroll
            for (int it = 0; it < 16; ++it) sum += key_val(sFinal[it]);
            s_keep = (sum / 16.0f > 0.5f) ? 1.0f : 0.0f;
        }
    }
    __syncthreads();

    if (tid < 16) {
        const u64 k = sFinal[tid];
        const int c = (int)(~(unsigned)(k & 0xffffffffu));
        out[(size_t)row * NN + c] = key_val(k) * s_keep;
    }
}

// ---------------------------------------------------------------------------
extern "C" void kernel_launch(void* const* d_in, const int* in_sizes, int n_in,
                              void* d_out, int out_size)
{
    const float* x_img = (const float*)d_in[0];
    const float* W_img = (const float*)d_in[1];
    const float* b_img = (const float*)d_in[2];
    const float* x_txt = (const float*)d_in[3];
    const float* W_txt = (const float*)d_in[4];
    const float* b_txt = (const float*)d_in[5];
    const float* x_aud = (const float*)d_in[6];
    const float* W_aud = (const float*)d_in[7];
    const float* b_aud = (const float*)d_in[8];
    float* out = (float*)d_out;

    cudaFuncSetAttribute(sim_mma_kernel, cudaFuncAttributeMaxDynamicSharedMemorySize, SIM_SMEM);

    enc_kernel<<<dim3(2, 64), 256>>>(x_img, W_img, b_img,
                                     x_txt, W_txt, b_txt,
                                     x_aud, W_aud, b_aud);
    norm_kernel<<<1024, 256>>>();
    sim_mma_kernel<<<dim3(64, 64), 256, SIM_SMEM>>>(out);
    topk_kernel<<<NN, 256>>>(out);
}